// round 1
// baseline (speedup 1.0000x reference)
#include <cuda_runtime.h>

// CrossAttention with seqlen-1 K/V broadcast:
//   out[b,t,:] = (visual_features[b] @ Wv + bv) @ Wp + bp   for every t.
// (softmax over T identical logits is exactly uniform; averaging T identical
//  value rows returns the row). x/Wq/Wk are mathematically irrelevant.

#define CC 1024
#define BB 4
#define TT_TOTAL 1024
#define SPLITK 16
#define KCH (CC / SPLITK)   // 64 K-rows per split block

// scratch (no allocations allowed -> __device__ globals)
__device__ float g_part[SPLITK][BB * CC];   // partial GEMM sums
__device__ float g_vec[BB * CC];            // reduced intermediate (z = vf@Wv+bv)

// Partial GEMM: part[split][b*C + j] = sum_{i in split} inp[b][i] * W[i][j]
// grid = (C/128, SPLITK), block = 128 threads. Coalesced W reads, no atomics.
__global__ void gemm_part_kernel(const float* __restrict__ inp,   // [BB][CC]
                                 const float* __restrict__ W)     // [CC][CC]
{
    __shared__ float s_in[BB][KCH];
    const int tid = threadIdx.x;                 // 0..127
    const int j   = blockIdx.x * 128 + tid;      // output column
    const int k0  = blockIdx.y * KCH;            // K chunk start

    for (int idx = tid; idx < BB * KCH; idx += 128) {
        int b = idx / KCH, i = idx % KCH;
        s_in[b][i] = inp[b * CC + k0 + i];
    }
    __syncthreads();

    float acc0 = 0.f, acc1 = 0.f, acc2 = 0.f, acc3 = 0.f;
    const float* __restrict__ Wp = W + (size_t)k0 * CC + j;
    #pragma unroll 8
    for (int i = 0; i < KCH; i++) {
        float wv = Wp[(size_t)i * CC];
        acc0 += s_in[0][i] * wv;
        acc1 += s_in[1][i] * wv;
        acc2 += s_in[2][i] * wv;
        acc3 += s_in[3][i] * wv;
    }
    float* p = &g_part[blockIdx.y][0];
    p[0 * CC + j] = acc0;
    p[1 * CC + j] = acc1;
    p[2 * CC + j] = acc2;
    p[3 * CC + j] = acc3;
}

// Reduce partials + bias -> g_vec.  grid = 16, block = 256 (covers BB*CC=4096).
__global__ void reduce_bias_kernel(const float* __restrict__ bias)
{
    const int idx = blockIdx.x * 256 + threadIdx.x;   // 0..4095
    float s = bias[idx & (CC - 1)];
    #pragma unroll
    for (int sp = 0; sp < SPLITK; sp++) s += g_part[sp][idx];
    g_vec[idx] = s;
}

// Final: w[b][c] = bp[c] + sum_sp g_part[sp][b*C+c]; broadcast over T rows.
// grid = BB * (T/ROWS_PER_BLK), block = 256 threads (each owns 4 consecutive c).
#define ROWS_PER_BLK 16
__global__ void bcast_kernel(const float* __restrict__ bp,
                             float* __restrict__ out)   // [BB][T][CC]
{
    const int blocks_per_b = TT_TOTAL / ROWS_PER_BLK;   // 64
    const int b  = blockIdx.x / blocks_per_b;
    const int t0 = (blockIdx.x % blocks_per_b) * ROWS_PER_BLK;
    const int c  = threadIdx.x * 4;

    float4 w;
    float* wf = reinterpret_cast<float*>(&w);
    #pragma unroll
    for (int u = 0; u < 4; u++) {
        float s = bp[c + u];
        #pragma unroll
        for (int sp = 0; sp < SPLITK; sp++) s += g_part[sp][b * CC + c + u];
        wf[u] = s;
    }

    float4* o = reinterpret_cast<float4*>(out + (size_t)b * TT_TOTAL * CC
                                              + (size_t)t0 * CC) + threadIdx.x;
    #pragma unroll
    for (int t = 0; t < ROWS_PER_BLK; t++) {
        o[(size_t)t * (CC / 4)] = w;
    }
}

extern "C" void kernel_launch(void* const* d_in, const int* in_sizes, int n_in,
                              void* d_out, int out_size)
{
    // metadata order: x, visual_features, Wq, bq, Wk, bk, Wv, bv, Wp, bp
    const float* vf = (const float*)d_in[1];
    const float* Wv = (const float*)d_in[6];
    const float* bv = (const float*)d_in[7];
    const float* Wp = (const float*)d_in[8];
    const float* bp = (const float*)d_in[9];
    float* out = (float*)d_out;

    float* g_vec_ptr = nullptr;
    cudaGetSymbolAddress((void**)&g_vec_ptr, g_vec);

    dim3 ggrid(CC / 128, SPLITK);

    // z = vf @ Wv + bv
    gemm_part_kernel<<<ggrid, 128>>>(vf, Wv);
    reduce_bias_kernel<<<(BB * CC) / 256, 256>>>(bv);
    // w = z @ Wp  (partials), then reduce+bp+broadcast fused
    gemm_part_kernel<<<ggrid, 128>>>(g_vec_ptr, Wp);
    bcast_kernel<<<BB * (TT_TOTAL / ROWS_PER_BLK), 256>>>(bp, out);
}

// round 4
// speedup vs baseline: 1.3957x; 1.3957x over previous
#include <cuda_runtime.h>

// CrossAttention with seqlen-1 K/V broadcast:
//   out[b,t,:] = (visual_features[b] @ Wv + bv) @ Wp + bp   for every t.
// Softmax over T identical logits is exactly uniform; averaging T identical
// value rows returns the row. x/Wq/Wk are mathematically irrelevant.
//
// Pipeline (4 graph nodes):
//   1) gemm1:  g_part[sp]  = partial(vf @ Wv)          grid(8,32)x128
//   2) gemm2:  z-slice reduce (+bv) in prologue, then
//              g_part2[sp] = partial(z @ Wp)           grid(8,32)x128
//   3) wred:   g_w = bp + sum_sp g_part2               grid(16)x256
//   4) bcast:  out[b,t,:] = g_w[b,:]  (pure streaming) grid(1024)x256

#define CC 1024
#define BB 4
#define TT_TOTAL 1024
#define SPLITK 32
#define KCH (CC / SPLITK)   // 32 K-rows per split block

__device__ float g_part [SPLITK][BB * CC];  // partials of vf@Wv
__device__ float g_part2[SPLITK][BB * CC];  // partials of z@Wp
__device__ float g_w[BB * CC];              // final w = z@Wp + bp

// ---------------------------------------------------------------------------
// Kernel 1: partial GEMM  part[sp][b*C+j] = sum_{i in sp-chunk} vf[b][i]*Wv[i][j]
// grid = (C/128, SPLITK), 128 threads.
__global__ void gemm1_kernel(const float* __restrict__ vf,   // [BB][CC]
                             const float* __restrict__ W)    // [CC][CC]
{
    __shared__ float s_in[BB][KCH];
    const int tid = threadIdx.x;             // 0..127
    const int j   = blockIdx.x * 128 + tid;
    const int k0  = blockIdx.y * KCH;

    // 128 threads load exactly BB*KCH = 128 inputs
    {
        int b = tid >> 5, i = tid & 31;
        s_in[b][i] = vf[b * CC + k0 + i];
    }
    __syncthreads();

    float a0 = 0.f, a1 = 0.f, a2 = 0.f, a3 = 0.f;
    const float* __restrict__ Wc = W + (size_t)k0 * CC + j;
    #pragma unroll
    for (int i = 0; i < KCH; i++) {
        float wv = Wc[(size_t)i * CC];
        a0 += s_in[0][i] * wv;
        a1 += s_in[1][i] * wv;
        a2 += s_in[2][i] * wv;
        a3 += s_in[3][i] * wv;
    }
    float* p = &g_part[blockIdx.y][0];
    p[0 * CC + j] = a0;
    p[1 * CC + j] = a1;
    p[2 * CC + j] = a2;
    p[3 * CC + j] = a3;
}

// ---------------------------------------------------------------------------
// Kernel 2: fused z-slice reduce + partial GEMM for w = z @ Wp
// Each block reduces the z values it needs (z[b][k0:k0+KCH]) from g_part.
__global__ void gemm2_kernel(const float* __restrict__ bv,
                             const float* __restrict__ W)    // Wp [CC][CC]
{
    __shared__ float s_z[BB][KCH];
    const int tid = threadIdx.x;             // 0..127
    const int j   = blockIdx.x * 128 + tid;
    const int k0  = blockIdx.y * KCH;

    // reduce the needed z slice: 128 threads <-> 128 (b,i) pairs
    {
        int b = tid >> 5, i = tid & 31;
        float s = bv[k0 + i];
        #pragma unroll
        for (int sp = 0; sp < SPLITK; sp++)
            s += g_part[sp][b * CC + k0 + i];
        s_z[b][i] = s;
    }
    __syncthreads();

    float a0 = 0.f, a1 = 0.f, a2 = 0.f, a3 = 0.f;
    const float* __restrict__ Wc = W + (size_t)k0 * CC + j;
    #pragma unroll
    for (int i = 0; i < KCH; i++) {
        float wv = Wc[(size_t)i * CC];
        a0 += s_z[0][i] * wv;
        a1 += s_z[1][i] * wv;
        a2 += s_z[2][i] * wv;
        a3 += s_z[3][i] * wv;
    }
    float* p = &g_part2[blockIdx.y][0];
    p[0 * CC + j] = a0;
    p[1 * CC + j] = a1;
    p[2 * CC + j] = a2;
    p[3 * CC + j] = a3;
}

// ---------------------------------------------------------------------------
// Kernel 3: w = bp + sum_sp g_part2   (4096 elements)
__global__ void wred_kernel(const float* __restrict__ bp)
{
    const int idx = blockIdx.x * 256 + threadIdx.x;  // 0..4095
    float s = bp[idx & (CC - 1)];
    #pragma unroll
    for (int sp = 0; sp < SPLITK; sp++) s += g_part2[sp][idx];
    g_w[idx] = s;
}

// ---------------------------------------------------------------------------
// Kernel 4: pure-streaming broadcast. 1024 blocks x 256 threads.
// Each block: one b, 4 rows. Each thread: 1 LDG.128 + 4 STG.128.
#define ROWS_PER_BLK 4
__global__ void bcast_kernel(float* __restrict__ out)   // [BB][T][CC]
{
    const int blocks_per_b = TT_TOTAL / ROWS_PER_BLK;   // 256
    const int b  = blockIdx.x / blocks_per_b;
    const int t0 = (blockIdx.x % blocks_per_b) * ROWS_PER_BLK;

    const float4 wv = *(reinterpret_cast<const float4*>(&g_w[b * CC]) + threadIdx.x);

    float4* o = reinterpret_cast<float4*>(out + (size_t)b * TT_TOTAL * CC
                                              + (size_t)t0 * CC) + threadIdx.x;
    #pragma unroll
    for (int t = 0; t < ROWS_PER_BLK; t++)
        o[(size_t)t * (CC / 4)] = wv;
}

extern "C" void kernel_launch(void* const* d_in, const int* in_sizes, int n_in,
                              void* d_out, int out_size)
{
    // metadata order: x, visual_features, Wq, bq, Wk, bk, Wv, bv, Wp, bp
    const float* vf = (const float*)d_in[1];
    const float* Wv = (const float*)d_in[6];
    const float* bv = (const float*)d_in[7];
    const float* Wp = (const float*)d_in[8];
    const float* bp = (const float*)d_in[9];
    float* out = (float*)d_out;

    dim3 ggrid(CC / 128, SPLITK);
    gemm1_kernel<<<ggrid, 128>>>(vf, Wv);
    gemm2_kernel<<<ggrid, 128>>>(bv, Wp);
    wred_kernel<<<(BB * CC) / 256, 256>>>(bp);
    bcast_kernel<<<BB * (TT_TOTAL / ROWS_PER_BLK), 256>>>(out);
}